// round 2
// baseline (speedup 1.0000x reference)
#include <cuda_runtime.h>
#include <cstddef>

#define BATCH 2
#define CCH   256
#define NSP   8192          // D*H*W = 8*32*32
#define GROUPS 32
#define CPG    8            // CCH / GROUPS
#define GN_EPS 1e-5f

// ------------------------- scratch (static device globals; no allocs) -------
__device__ float g_h   [BATCH * CCH * NSP];          // 16 MB  groupnorm output
__device__ float g_qkv [BATCH * 3 * CCH * NSP];      // 48 MB  q|k|v
__device__ float g_S   [134217728];                  // 512 MB scores [B,N,N]
__device__ float g_hout[BATCH * CCH * NSP];          // 16 MB  attn output

// ------------------------- GroupNorm (fused stats + apply) ------------------
__global__ void groupnorm_kernel(const float* __restrict__ x,
                                 const float* __restrict__ w,
                                 const float* __restrict__ b,
                                 float* __restrict__ h)
{
    const int blk = blockIdx.x;            // b*GROUPS + g  (64 blocks)
    const int g   = blk % GROUPS;
    const size_t base = (size_t)blk * (CPG * NSP);
    const int tid = threadIdx.x;           // 512 threads
    const int GSZ = CPG * NSP;             // 65536 contiguous floats

    const float4* x4 = (const float4*)(x + base);
    float s = 0.f, ss = 0.f;
    for (int i = tid; i < GSZ / 4; i += 512) {
        float4 v = x4[i];
        s  += v.x + v.y + v.z + v.w;
        ss += v.x*v.x + v.y*v.y + v.z*v.z + v.w*v.w;
    }
    __shared__ float rs[16], rss[16];
    #pragma unroll
    for (int o = 16; o > 0; o >>= 1) {
        s  += __shfl_down_sync(0xffffffffu, s,  o);
        ss += __shfl_down_sync(0xffffffffu, ss, o);
    }
    if ((tid & 31) == 0) { rs[tid >> 5] = s; rss[tid >> 5] = ss; }
    __syncthreads();
    if (tid < 32) {
        s  = (tid < 16) ? rs[tid]  : 0.f;
        ss = (tid < 16) ? rss[tid] : 0.f;
        #pragma unroll
        for (int o = 8; o > 0; o >>= 1) {
            s  += __shfl_down_sync(0xffffffffu, s,  o);
            ss += __shfl_down_sync(0xffffffffu, ss, o);
        }
        if (tid == 0) { rs[0] = s; rss[0] = ss; }
    }
    __syncthreads();
    const float mean = rs[0] / (float)GSZ;
    const float var  = rss[0] / (float)GSZ - mean * mean;
    const float rstd = rsqrtf(var + GN_EPS);

    float4* h4 = (float4*)(h + base);
    for (int i = tid; i < GSZ / 4; i += 512) {
        int c = g * CPG + (i * 4) / NSP;   // NSP % 4 == 0 -> one channel per float4
        float sc = w[c] * rstd;
        float of = b[c] - mean * sc;
        float4 v = x4[i];
        v.x = v.x * sc + of; v.y = v.y * sc + of;
        v.z = v.z * sc + of; v.w = v.w * sc + of;
        h4[i] = v;
    }
}

// ------------------------- tiled fp32 GEMM: 128x128x8, 8x8 microtile --------
// C[m,n] = alpha * sum_k A(m,k)*B(k,n) + bias[m] (+ resid[m,n])
// TA=false: A row-major [M,K] (A[m*lda+k]); TA=true: A stored [K,M] (A[k*lda+m])
// TB=false: B stored [K,N] (B[k*ldb+n]);    TB=true: B row-major [N,K] (B[n*ldb+k])
// 256 threads. Requires M%128==0, N%128==0, K%8==0, all float4-aligned.
template<bool TA, bool TB>
__global__ __launch_bounds__(256, 2)
void gemm_kernel(const float* __restrict__ A,
                 const float* __restrict__ B,
                 float* __restrict__ Cout,
                 int M, int N, int K, int lda, int ldb, int ldc,
                 long long strA, long long strB, long long strC,
                 float alpha,
                 const float* __restrict__ bias,
                 const float* __restrict__ resid, long long strR)
{
    __shared__ float As[8][128];
    __shared__ float Bs[8][128];

    const int bz = blockIdx.z;
    A    += (size_t)bz * strA;
    B    += (size_t)bz * strB;
    Cout += (size_t)bz * strC;
    if (resid) resid += (size_t)bz * strR;

    const int m0 = blockIdx.y * 128;
    const int n0 = blockIdx.x * 128;
    const int tid = threadIdx.x;
    const int tx = tid & 15, ty = tid >> 4;      // 16x16 thread grid

    float acc[8][8] = {};

    for (int k0 = 0; k0 < K; k0 += 8) {
        if (TA) {   // A[k*lda+m]: direct coalesced float4
            int k = tid >> 5, m = (tid & 31) * 4;
            float4 v = *(const float4*)&A[(size_t)(k0 + k) * lda + m0 + m];
            *(float4*)&As[k][m] = v;
        } else {    // A[m*lda+k]: transpose into smem
            int m = tid >> 1, kc = (tid & 1) * 4;
            float4 v = *(const float4*)&A[(size_t)(m0 + m) * lda + k0 + kc];
            As[kc + 0][m] = v.x; As[kc + 1][m] = v.y;
            As[kc + 2][m] = v.z; As[kc + 3][m] = v.w;
        }
        if (!TB) {  // B[k*ldb+n]: direct coalesced float4
            int k = tid >> 5, n = (tid & 31) * 4;
            float4 v = *(const float4*)&B[(size_t)(k0 + k) * ldb + n0 + n];
            *(float4*)&Bs[k][n] = v;
        } else {    // B[n*ldb+k]: transpose into smem
            int n = tid >> 1, kc = (tid & 1) * 4;
            float4 v = *(const float4*)&B[(size_t)(n0 + n) * ldb + k0 + kc];
            Bs[kc + 0][n] = v.x; Bs[kc + 1][n] = v.y;
            Bs[kc + 2][n] = v.z; Bs[kc + 3][n] = v.w;
        }
        __syncthreads();
        #pragma unroll
        for (int k = 0; k < 8; k++) {
            float a[8], b[8];
            *(float4*)&a[0] = *(const float4*)&As[k][ty * 8];
            *(float4*)&a[4] = *(const float4*)&As[k][ty * 8 + 4];
            *(float4*)&b[0] = *(const float4*)&Bs[k][tx * 8];
            *(float4*)&b[4] = *(const float4*)&Bs[k][tx * 8 + 4];
            #pragma unroll
            for (int i = 0; i < 8; i++)
                #pragma unroll
                for (int j = 0; j < 8; j++)
                    acc[i][j] += a[i] * b[j];
        }
        __syncthreads();
    }

    #pragma unroll
    for (int i = 0; i < 8; i++) {
        int m = m0 + ty * 8 + i;
        float bs = bias ? bias[m] : 0.f;
        float v[8];
        #pragma unroll
        for (int j = 0; j < 8; j++) v[j] = alpha * acc[i][j] + bs;
        size_t off = (size_t)m * ldc + n0 + tx * 8;
        if (resid) {
            float4 r0 = *(const float4*)&resid[off];
            float4 r1 = *(const float4*)&resid[off + 4];
            v[0] += r0.x; v[1] += r0.y; v[2] += r0.z; v[3] += r0.w;
            v[4] += r1.x; v[5] += r1.y; v[6] += r1.z; v[7] += r1.w;
        }
        *(float4*)&Cout[off]     = make_float4(v[0], v[1], v[2], v[3]);
        *(float4*)&Cout[off + 4] = make_float4(v[4], v[5], v[6], v[7]);
    }
}

// ------------------------- row softmax (8192 per row, staged in smem) --------
__global__ void softmax_kernel(float* __restrict__ S)
{
    __shared__ float row[NSP];         // 32 KB
    __shared__ float red[8];
    const size_t base = (size_t)blockIdx.x * NSP;
    const int tid = threadIdx.x;       // 256 threads = 8 warps

    float4* r4 = (float4*)row;
    float4* s4 = (float4*)(S + base);

    float mx = -1e30f;
    for (int i = tid; i < NSP / 4; i += 256) {
        float4 v = s4[i];
        r4[i] = v;
        mx = fmaxf(mx, fmaxf(fmaxf(v.x, v.y), fmaxf(v.z, v.w)));
    }
    #pragma unroll
    for (int o = 16; o > 0; o >>= 1) mx = fmaxf(mx, __shfl_xor_sync(0xffffffffu, mx, o));
    if ((tid & 31) == 0) red[tid >> 5] = mx;
    __syncthreads();
    if (tid == 0) {
        float m = red[0];
        #pragma unroll
        for (int i = 1; i < 8; i++) m = fmaxf(m, red[i]);
        red[0] = m;
    }
    __syncthreads();
    const float bmax = red[0];
    __syncthreads();

    float sum = 0.f;
    for (int i = tid; i < NSP / 4; i += 256) {
        float4 v = r4[i];
        v.x = __expf(v.x - bmax); v.y = __expf(v.y - bmax);
        v.z = __expf(v.z - bmax); v.w = __expf(v.w - bmax);
        r4[i] = v;
        sum += v.x + v.y + v.z + v.w;
    }
    #pragma unroll
    for (int o = 16; o > 0; o >>= 1) sum += __shfl_xor_sync(0xffffffffu, sum, o);
    if ((tid & 31) == 0) red[tid >> 5] = sum;
    __syncthreads();
    if (tid == 0) {
        float t = 0.f;
        #pragma unroll
        for (int i = 0; i < 8; i++) t += red[i];
        red[0] = t;
    }
    __syncthreads();
    const float inv = 1.f / red[0];
    for (int i = tid; i < NSP / 4; i += 256) {
        float4 v = r4[i];
        v.x *= inv; v.y *= inv; v.z *= inv; v.w *= inv;
        s4[i] = v;
    }
}

// ------------------------- launch ------------------------------------------
extern "C" void kernel_launch(void* const* d_in, const int* in_sizes, int n_in,
                              void* d_out, int out_size)
{
    const float* x      = (const float*)d_in[0];
    const float* norm_w = (const float*)d_in[1];
    const float* norm_b = (const float*)d_in[2];
    const float* qkv_w  = (const float*)d_in[3];
    const float* qkv_b  = (const float*)d_in[4];
    const float* proj_w = (const float*)d_in[5];
    const float* proj_b = (const float*)d_in[6];
    float* out = (float*)d_out;

    float *h, *qkv, *S, *hout;
    cudaGetSymbolAddress((void**)&h,    g_h);
    cudaGetSymbolAddress((void**)&qkv,  g_qkv);
    cudaGetSymbolAddress((void**)&S,    g_S);
    cudaGetSymbolAddress((void**)&hout, g_hout);

    const long long CN   = (long long)CCH * NSP;       // 2,097,152
    const long long C3N  = 3LL * CN;                   // 6,291,456
    const long long NN   = (long long)NSP * NSP;       // 67,108,864
    const float scale = 0.0625f;                       // C^-0.5 = 1/16

    // 1) GroupNorm
    groupnorm_kernel<<<BATCH * GROUPS, 512>>>(x, norm_w, norm_b, h);

    // 2) QKV projection: [768,256] @ [256,8192] per batch (+bias)
    {
        dim3 grid(NSP / 128, (3 * CCH) / 128, BATCH);
        gemm_kernel<false, false><<<grid, 256>>>(
            qkv_w, h, qkv, 3 * CCH, NSP, CCH, CCH, NSP, NSP,
            0LL, CN, C3N, 1.f, qkv_b, nullptr, 0LL);
    }

    // 3) S = scale * q^T k : M=N=8192, K=256 (TA: q stored [C,N]; TB=false: k stored [C,N])
    {
        dim3 grid(NSP / 128, NSP / 128, BATCH);
        gemm_kernel<true, false><<<grid, 256>>>(
            qkv, qkv + CN, S, NSP, NSP, CCH, NSP, NSP, NSP,
            C3N, C3N, NN, scale, nullptr, nullptr, 0LL);
    }

    // 4) row softmax over m
    softmax_kernel<<<BATCH * NSP, 256>>>(S);

    // 5) hout[c,n] = sum_m S[n,m] v[c,m] : M=256, N=8192, K=8192 (TB: S row-major [N,K])
    {
        dim3 grid(NSP / 128, CCH / 128, BATCH);
        gemm_kernel<false, true><<<grid, 256>>>(
            qkv + 2 * CN, S, hout, CCH, NSP, NSP, NSP, NSP, NSP,
            C3N, NN, CN, 1.f, nullptr, nullptr, 0LL);
    }

    // 6) out = x + proj_w @ hout + proj_b
    {
        dim3 grid(NSP / 128, CCH / 128, BATCH);
        gemm_kernel<false, false><<<grid, 256>>>(
            proj_w, hout, out, CCH, NSP, CCH, CCH, NSP, NSP,
            0LL, CN, CN, 1.f, proj_b, x, CN);
    }
}

// round 14
// speedup vs baseline: 2.5643x; 2.5643x over previous
#include <cuda_runtime.h>
#include <cstdint>
#include <cstddef>

#define BATCH 2
#define CCH   256
#define NSP   8192
#define GROUPS 32
#define CPG    8
#define GN_EPS 1e-5f

// ---------------- scratch (static device globals; no allocs) ----------------
__device__ float g_h   [BATCH * NSP * CCH];        // 16 MB  [B,N,C] token-major
__device__ float g_qkv [BATCH * NSP * 3 * CCH];    // 48 MB  [B,N,768]
__device__ float g_S   [134217728];                // 512 MB [B,N,N]
__device__ float g_vT  [BATCH * CCH * NSP];        // 16 MB  [B,C,N]
__device__ float g_hout[BATCH * NSP * CCH];        // 16 MB  [B,N,C]

// ---------------- tf32 helpers (plain sm_103-safe PTX, no 'a' features) -----
__device__ __forceinline__ float to_tf32(float x) {
    float r;
    asm("cvt.rna.tf32.f32 %0, %1;" : "=f"(r) : "f"(x));
    return r;
}
__device__ __forceinline__ void mma16n8k8(float* d, const float* a, const float* b) {
    asm volatile(
        "mma.sync.aligned.m16n8k8.row.col.f32.tf32.tf32.f32 "
        "{%0,%1,%2,%3}, {%4,%5,%6,%7}, {%8,%9}, {%0,%1,%2,%3};"
        : "+f"(d[0]), "+f"(d[1]), "+f"(d[2]), "+f"(d[3])
        : "r"(__float_as_uint(a[0])), "r"(__float_as_uint(a[1])),
          "r"(__float_as_uint(a[2])), "r"(__float_as_uint(a[3])),
          "r"(__float_as_uint(b[0])), "r"(__float_as_uint(b[1])));
}

// ---------------- GroupNorm -> token-major h [B,N,C] ----------------
__global__ void groupnorm_t_kernel(const float* __restrict__ x,
                                   const float* __restrict__ w,
                                   const float* __restrict__ b,
                                   float* __restrict__ h)
{
    const int blk = blockIdx.x;                 // b*GROUPS + g
    const int bi  = blk / GROUPS;
    const int g   = blk % GROUPS;
    const size_t xbase = (size_t)blk * (CPG * NSP);
    const int tid = threadIdx.x;                // 256

    const float4* x4 = (const float4*)(x + xbase);
    float s = 0.f, ss = 0.f;
    for (int i = tid; i < (CPG * NSP) / 4; i += 256) {
        float4 v = x4[i];
        s  += v.x + v.y + v.z + v.w;
        ss += v.x*v.x + v.y*v.y + v.z*v.z + v.w*v.w;
    }
    __shared__ float rs[8], rss[8];
    #pragma unroll
    for (int o = 16; o > 0; o >>= 1) {
        s  += __shfl_down_sync(0xffffffffu, s,  o);
        ss += __shfl_down_sync(0xffffffffu, ss, o);
    }
    if ((tid & 31) == 0) { rs[tid >> 5] = s; rss[tid >> 5] = ss; }
    __syncthreads();
    if (tid == 0) {
        float a = 0.f, c = 0.f;
        #pragma unroll
        for (int i = 0; i < 8; i++) { a += rs[i]; c += rss[i]; }
        rs[0] = a; rss[0] = c;
    }
    __syncthreads();
    const float mean = rs[0] / (float)(CPG * NSP);
    const float var  = rss[0] / (float)(CPG * NSP) - mean * mean;
    const float rstd = rsqrtf(var + GN_EPS);

    // pass 2: transpose 8xNSP -> h[token][g*8 + c]
    __shared__ float smt[8][136];
    const int c  = tid >> 5;         // 0..7
    const int q  = tid & 31;
    const float sc = w[g * CPG + c] * rstd;
    const float of = b[g * CPG + c] - mean * sc;
    float* hb = h + (size_t)bi * NSP * CCH;
    const int half = tid & 1;
    const int nn   = tid >> 1;       // 0..127

    for (int t = 0; t < NSP / 128; t++) {
        float4 v = *(const float4*)&x[xbase + (size_t)c * NSP + t * 128 + q * 4];
        v.x = v.x * sc + of; v.y = v.y * sc + of;
        v.z = v.z * sc + of; v.w = v.w * sc + of;
        *(float4*)&smt[c][q * 4] = v;
        __syncthreads();
        float4 o;
        o.x = smt[half * 4 + 0][nn];
        o.y = smt[half * 4 + 1][nn];
        o.z = smt[half * 4 + 2][nn];
        o.w = smt[half * 4 + 3][nn];
        *(float4*)&hb[(size_t)(t * 128 + nn) * CCH + g * CPG + half * 4] = o;
        __syncthreads();
    }
}

// ---------------- tf32 mma.sync GEMM: D[m,n] = alpha*sum_k A[m,k]B[n,k] -----
// BM=BN=128, BK=16. A [M,K] lda; B [N,K] ldb; C [M,N] ldc. All K-major.
// 256 threads = 8 warps (2 m x 4 n), warp tile 64x32, mma m16n8k8 tf32.
#define GM_PAD 20   // smem row stride in words: banks (20*g + t) mod 32 distinct

__global__ __launch_bounds__(256, 2)
void tgemm_kernel(const float* __restrict__ A, const float* __restrict__ B,
                  float* __restrict__ C,
                  int K, int lda, int ldb, int ldc,
                  long long strA, long long strB, long long strC,
                  float alpha,
                  const float* __restrict__ bias_m,
                  const float* __restrict__ bias_n,
                  const float* __restrict__ resid, long long strR)
{
    __shared__ float As[2][128 * GM_PAD];   // 10 KB each buf
    __shared__ float Bs[2][128 * GM_PAD];

    const int tid = threadIdx.x;
    const int bz = blockIdx.z;
    A += (size_t)bz * strA;
    B += (size_t)bz * strB;
    C += (size_t)bz * strC;
    if (resid) resid += (size_t)bz * strR;
    const int m0 = blockIdx.y * 128;
    const int n0 = blockIdx.x * 128;

    const int warp = tid >> 5, lane = tid & 31;
    const int wm = warp & 1, wn = warp >> 1;     // 2 x 4 warps
    const int g = lane >> 2, t = lane & 3;       // fragment coords
    const int lr = tid >> 2, kc = (tid & 3) * 4; // gmem tile loader coords

    float d[4][4][4];
    #pragma unroll
    for (int i = 0; i < 4; i++)
        #pragma unroll
        for (int j = 0; j < 4; j++)
            #pragma unroll
            for (int r = 0; r < 4; r++) d[i][j][r] = 0.f;

    const int nk = K / 16;
    float4 pa0, pa1, pb0, pb1;

    // load + store tile 0
    pa0 = *(const float4*)&A[(size_t)(m0 + lr)      * lda + kc];
    pa1 = *(const float4*)&A[(size_t)(m0 + lr + 64) * lda + kc];
    pb0 = *(const float4*)&B[(size_t)(n0 + lr)      * ldb + kc];
    pb1 = *(const float4*)&B[(size_t)(n0 + lr + 64) * ldb + kc];
    {
        float4 v;
        v = make_float4(to_tf32(pa0.x), to_tf32(pa0.y), to_tf32(pa0.z), to_tf32(pa0.w));
        *(float4*)&As[0][lr * GM_PAD + kc] = v;
        v = make_float4(to_tf32(pa1.x), to_tf32(pa1.y), to_tf32(pa1.z), to_tf32(pa1.w));
        *(float4*)&As[0][(lr + 64) * GM_PAD + kc] = v;
        v = make_float4(to_tf32(pb0.x), to_tf32(pb0.y), to_tf32(pb0.z), to_tf32(pb0.w));
        *(float4*)&Bs[0][lr * GM_PAD + kc] = v;
        v = make_float4(to_tf32(pb1.x), to_tf32(pb1.y), to_tf32(pb1.z), to_tf32(pb1.w));
        *(float4*)&Bs[0][(lr + 64) * GM_PAD + kc] = v;
    }
    __syncthreads();

    for (int kt = 0; kt < nk; kt++) {
        const int buf = kt & 1;
        if (kt + 1 < nk) {
            const int k0 = (kt + 1) * 16;
            pa0 = *(const float4*)&A[(size_t)(m0 + lr)      * lda + k0 + kc];
            pa1 = *(const float4*)&A[(size_t)(m0 + lr + 64) * lda + k0 + kc];
            pb0 = *(const float4*)&B[(size_t)(n0 + lr)      * ldb + k0 + kc];
            pb1 = *(const float4*)&B[(size_t)(n0 + lr + 64) * ldb + k0 + kc];
        }
        #pragma unroll
        for (int ks = 0; ks < 16; ks += 8) {
            float af[4][4], bf[4][2];
            #pragma unroll
            for (int mt = 0; mt < 4; mt++) {
                const float* ap = &As[buf][(wm * 64 + mt * 16 + g) * GM_PAD + ks + t];
                af[mt][0] = ap[0];
                af[mt][1] = ap[8 * GM_PAD];
                af[mt][2] = ap[4];
                af[mt][3] = ap[8 * GM_PAD + 4];
            }
            #pragma unroll
            for (int nt = 0; nt < 4; nt++) {
                const float* bp = &Bs[buf][(wn * 32 + nt * 8 + g) * GM_PAD + ks + t];
                bf[nt][0] = bp[0];
                bf[nt][1] = bp[4];
            }
            #pragma unroll
            for (int mt = 0; mt < 4; mt++)
                #pragma unroll
                for (int nt = 0; nt < 4; nt++)
                    mma16n8k8(d[mt][nt], af[mt], bf[nt]);
        }
        if (kt + 1 < nk) {
            __syncthreads();
            const int nb = buf ^ 1;
            float4 v;
            v = make_float4(to_tf32(pa0.x), to_tf32(pa0.y), to_tf32(pa0.z), to_tf32(pa0.w));
            *(float4*)&As[nb][lr * GM_PAD + kc] = v;
            v = make_float4(to_tf32(pa1.x), to_tf32(pa1.y), to_tf32(pa1.z), to_tf32(pa1.w));
            *(float4*)&As[nb][(lr + 64) * GM_PAD + kc] = v;
            v = make_float4(to_tf32(pb0.x), to_tf32(pb0.y), to_tf32(pb0.z), to_tf32(pb0.w));
            *(float4*)&Bs[nb][lr * GM_PAD + kc] = v;
            v = make_float4(to_tf32(pb1.x), to_tf32(pb1.y), to_tf32(pb1.z), to_tf32(pb1.w));
            *(float4*)&Bs[nb][(lr + 64) * GM_PAD + kc] = v;
            __syncthreads();
        }
    }

    // epilogue: D fragment rows g/g+8, cols 2t/2t+1 per 16x8 tile
    #pragma unroll
    for (int mt = 0; mt < 4; mt++) {
        #pragma unroll
        for (int h = 0; h < 2; h++) {
            const int m = m0 + wm * 64 + mt * 16 + g + h * 8;
            const float bm = bias_m ? bias_m[m] : 0.f;
            #pragma unroll
            for (int nt = 0; nt < 4; nt++) {
                const int n = n0 + wn * 32 + nt * 8 + t * 2;
                const size_t off = (size_t)m * ldc + n;
                float v0 = d[mt][nt][h * 2 + 0] * alpha + bm;
                float v1 = d[mt][nt][h * 2 + 1] * alpha + bm;
                if (bias_n) { v0 += bias_n[n]; v1 += bias_n[n + 1]; }
                if (resid)  { v0 += resid[off]; v1 += resid[off + 1]; }
                *(float2*)&C[off] = make_float2(v0, v1);
            }
        }
    }
}

// ---------------- v transpose: qkv[:, :, 512:768] -> vT [B,C,N] -------------
__global__ void transpose_v_kernel(const float* __restrict__ qkv,
                                   float* __restrict__ vT)
{
    __shared__ float t[32][33];
    const int b = blockIdx.z;
    const int n0 = blockIdx.y * 32;
    const int c0 = blockIdx.x * 32;
    const float* src = qkv + (size_t)b * NSP * 3 * CCH;
    float* dst = vT + (size_t)b * CCH * NSP;
    const int x = threadIdx.x, y = threadIdx.y;   // 32x8
    #pragma unroll
    for (int j = 0; j < 32; j += 8)
        t[y + j][x] = src[(size_t)(n0 + y + j) * (3 * CCH) + 2 * CCH + c0 + x];
    __syncthreads();
    #pragma unroll
    for (int j = 0; j < 32; j += 8)
        dst[(size_t)(c0 + y + j) * NSP + n0 + x] = t[x][y + j];
}

// ---------------- row softmax ----------------
__global__ void softmax_kernel(float* __restrict__ S)
{
    __shared__ float row[NSP];
    __shared__ float red[8];
    const size_t base = (size_t)blockIdx.x * NSP;
    const int tid = threadIdx.x;

    float4* r4 = (float4*)row;
    float4* s4 = (float4*)(S + base);

    float mx = -1e30f;
    for (int i = tid; i < NSP / 4; i += 256) {
        float4 v = s4[i];
        r4[i] = v;
        mx = fmaxf(mx, fmaxf(fmaxf(v.x, v.y), fmaxf(v.z, v.w)));
    }
    #pragma unroll
    for (int o = 16; o > 0; o >>= 1) mx = fmaxf(mx, __shfl_xor_sync(0xffffffffu, mx, o));
    if ((tid & 31) == 0) red[tid >> 5] = mx;
    __syncthreads();
    if (tid == 0) {
        float m = red[0];
        #pragma unroll
        for (int i = 1; i < 8; i++) m = fmaxf(m, red[i]);
        red[0] = m;
    }
    __syncthreads();
    const float bmax = red[0];
    __syncthreads();

    float sum = 0.f;
    for (int i = tid; i < NSP / 4; i += 256) {
        float4 v = r4[i];
        v.x = __expf(v.x - bmax); v.y = __expf(v.y - bmax);
        v.z = __expf(v.z - bmax); v.w = __expf(v.w - bmax);
        r4[i] = v;
        sum += v.x + v.y + v.z + v.w;
    }
    #pragma unroll
    for (int o = 16; o > 0; o >>= 1) sum += __shfl_xor_sync(0xffffffffu, sum, o);
    if ((tid & 31) == 0) red[tid >> 5] = sum;
    __syncthreads();
    if (tid == 0) {
        float tt = 0.f;
        #pragma unroll
        for (int i = 0; i < 8; i++) tt += red[i];
        red[0] = tt;
    }
    __syncthreads();
    const float inv = 1.f / red[0];
    for (int i = tid; i < NSP / 4; i += 256) {
        float4 v = r4[i];
        v.x *= inv; v.y *= inv; v.z *= inv; v.w *= inv;
        s4[i] = v;
    }
}

// ---------------- launch ----------------
extern "C" void kernel_launch(void* const* d_in, const int* in_sizes, int n_in,
                              void* d_out, int out_size)
{
    const float* x      = (const float*)d_in[0];
    const float* norm_w = (const float*)d_in[1];
    const float* norm_b = (const float*)d_in[2];
    const float* qkv_w  = (const float*)d_in[3];
    const float* qkv_b  = (const float*)d_in[4];
    const float* proj_w = (const float*)d_in[5];
    const float* proj_b = (const float*)d_in[6];
    float* out = (float*)d_out;

    float *h, *qkv, *S, *vT, *hout;
    cudaGetSymbolAddress((void**)&h,    g_h);
    cudaGetSymbolAddress((void**)&qkv,  g_qkv);
    cudaGetSymbolAddress((void**)&S,    g_S);
    cudaGetSymbolAddress((void**)&vT,   g_vT);
    cudaGetSymbolAddress((void**)&hout, g_hout);

    const long long CN  = (long long)CCH * NSP;       // 2,097,152
    const long long C3N = 3LL * CN;
    const long long NN  = (long long)NSP * NSP;
    const float scale = 0.0625f;                      // C^-0.5

    // 1) GroupNorm -> h [B,N,C]
    groupnorm_t_kernel<<<BATCH * GROUPS, 256>>>(x, norm_w, norm_b, h);

    // 2) qkv[token,o] = sum_c h[token,c] qkv_w[o,c] + qkv_b[o]
    {
        dim3 grid((3 * CCH) / 128, NSP / 128, BATCH);
        tgemm_kernel<<<grid, 256>>>(
            h, qkv_w, qkv, CCH, CCH, CCH, 3 * CCH,
            CN, 0LL, C3N, 1.f, nullptr, qkv_b, nullptr, 0LL);
    }

    // 3) S[nq,nk] = scale * sum_c q[nq,c] k[nk,c]
    {
        dim3 grid(NSP / 128, NSP / 128, BATCH);
        tgemm_kernel<<<grid, 256>>>(
            qkv, qkv + CCH, S, CCH, 3 * CCH, 3 * CCH, NSP,
            C3N, C3N, NN, scale, nullptr, nullptr, nullptr, 0LL);
    }

    // 4) softmax rows
    softmax_kernel<<<BATCH * NSP, 256>>>(S);

    // 5) vT [B,C,N]
    {
        dim3 grid(CCH / 32, NSP / 32, BATCH);
        transpose_v_kernel<<<grid, dim3(32, 8)>>>(qkv, vT);
    }

    // 6) hout[n,c] = sum_m S[n,m] vT[c,m]
    {
        dim3 grid(CCH / 128, NSP / 128, BATCH);
        tgemm_kernel<<<grid, 256>>>(
            S, vT, hout, NSP, NSP, NSP, CCH,
            NN, CN, CN, 1.f, nullptr, nullptr, nullptr, 0LL);
    }

    // 7) out[c_out,n] = sum_c proj_w[c_out,c] hout[n,c] + proj_b[c_out] + x
    {
        dim3 grid(NSP / 128, CCH / 128, BATCH);
        tgemm_kernel<<<grid, 256>>>(
            proj_w, hout, out, CCH, CCH, CCH, NSP,
            0LL, CN, CN, 1.f, proj_b, nullptr, x, CN);
    }
}

// round 16
// speedup vs baseline: 2.8530x; 1.1126x over previous
#include <cuda_runtime.h>
#include <cuda_bf16.h>
#include <cstdint>
#include <cstddef>

#define BATCH 2
#define CCH   256
#define NSP   8192
#define GROUPS 32
#define CPG    8
#define GN_EPS 1e-5f

// ---------------- scratch (static device globals; no allocs) ----------------
__device__ float g_h   [BATCH * NSP * CCH];        // 16 MB  [B,N,C] token-major
__device__ float g_qkv [BATCH * NSP * 3 * CCH];    // 48 MB  [B,N,768]
__device__ float g_S   [134217728];                // 512 MB [B,N,N]
__device__ float g_vT  [BATCH * CCH * NSP];        // 16 MB  [B,C,N]
__device__ float g_hout[BATCH * NSP * CCH];        // 16 MB  [B,N,C]

// ---------------- bf16 helpers (plain sm_103-safe, sm_80 baseline PTX) ------
__device__ __forceinline__ uint32_t pk_bf16(float a, float b) {
    __nv_bfloat162 h = __floats2bfloat162_rn(a, b);   // .x=a (low), .y=b (high)
    return *(uint32_t*)&h;
}
__device__ __forceinline__ void mma16n8k16(float* d, const uint32_t* a,
                                           uint32_t b0, uint32_t b1) {
    asm volatile(
        "mma.sync.aligned.m16n8k16.row.col.f32.bf16.bf16.f32 "
        "{%0,%1,%2,%3}, {%4,%5,%6,%7}, {%8,%9}, {%0,%1,%2,%3};"
        : "+f"(d[0]), "+f"(d[1]), "+f"(d[2]), "+f"(d[3])
        : "r"(a[0]), "r"(a[1]), "r"(a[2]), "r"(a[3]), "r"(b0), "r"(b1));
}

// ---------------- GroupNorm -> token-major h [B,N,C] ----------------
__global__ void groupnorm_t_kernel(const float* __restrict__ x,
                                   const float* __restrict__ w,
                                   const float* __restrict__ b,
                                   float* __restrict__ h)
{
    const int blk = blockIdx.x;                 // b*GROUPS + g
    const int bi  = blk / GROUPS;
    const int g   = blk % GROUPS;
    const size_t xbase = (size_t)blk * (CPG * NSP);
    const int tid = threadIdx.x;                // 256

    const float4* x4 = (const float4*)(x + xbase);
    float s = 0.f, ss = 0.f;
    for (int i = tid; i < (CPG * NSP) / 4; i += 256) {
        float4 v = x4[i];
        s  += v.x + v.y + v.z + v.w;
        ss += v.x*v.x + v.y*v.y + v.z*v.z + v.w*v.w;
    }
    __shared__ float rs[8], rss[8];
    #pragma unroll
    for (int o = 16; o > 0; o >>= 1) {
        s  += __shfl_down_sync(0xffffffffu, s,  o);
        ss += __shfl_down_sync(0xffffffffu, ss, o);
    }
    if ((tid & 31) == 0) { rs[tid >> 5] = s; rss[tid >> 5] = ss; }
    __syncthreads();
    if (tid == 0) {
        float a = 0.f, c = 0.f;
        #pragma unroll
        for (int i = 0; i < 8; i++) { a += rs[i]; c += rss[i]; }
        rs[0] = a; rss[0] = c;
    }
    __syncthreads();
    const float mean = rs[0] / (float)(CPG * NSP);
    const float var  = rss[0] / (float)(CPG * NSP) - mean * mean;
    const float rstd = rsqrtf(var + GN_EPS);

    // pass 2: transpose 8xNSP -> h[token][g*8 + c]
    __shared__ float smt[8][136];
    const int c  = tid >> 5;         // 0..7
    const int q  = tid & 31;
    const float sc = w[g * CPG + c] * rstd;
    const float of = b[g * CPG + c] - mean * sc;
    float* hb = h + (size_t)bi * NSP * CCH;
    const int half = tid & 1;
    const int nn   = tid >> 1;       // 0..127

    for (int t = 0; t < NSP / 128; t++) {
        float4 v = *(const float4*)&x[xbase + (size_t)c * NSP + t * 128 + q * 4];
        v.x = v.x * sc + of; v.y = v.y * sc + of;
        v.z = v.z * sc + of; v.w = v.w * sc + of;
        *(float4*)&smt[c][q * 4] = v;
        __syncthreads();
        float4 o;
        o.x = smt[half * 4 + 0][nn];
        o.y = smt[half * 4 + 1][nn];
        o.z = smt[half * 4 + 2][nn];
        o.w = smt[half * 4 + 3][nn];
        *(float4*)&hb[(size_t)(t * 128 + nn) * CCH + g * CPG + half * 4] = o;
        __syncthreads();
    }
}

// ---------------- bf16 mma.sync GEMM: D[m,n] = alpha*sum_k A[m,k]B[n,k] -----
// BM=BN=128, BK=16. A [M,K] lda; B [N,K] ldb; C [M,N] ldc (fp32 gmem).
// 256 threads = 8 warps (2 m x 4 n), warp tile 64x32, mma m16n8k16 bf16.
// Smem: packed bf16x2 words, row stride 12 words (8 data + 4 pad);
// fragment loads hit banks (12g + t) mod 32 = all distinct -> conflict-free.
#define GM_PAD 12

__global__ __launch_bounds__(256, 2)
void tgemm_kernel(const float* __restrict__ A, const float* __restrict__ B,
                  float* __restrict__ C,
                  int K, int lda, int ldb, int ldc,
                  long long strA, long long strB, long long strC,
                  float alpha,
                  const float* __restrict__ bias_m,
                  const float* __restrict__ bias_n,
                  const float* __restrict__ resid, long long strR)
{
    __shared__ uint32_t As[2][128 * GM_PAD];   // 6 KB each buf
    __shared__ uint32_t Bs[2][128 * GM_PAD];

    const int tid = threadIdx.x;
    const int bz = blockIdx.z;
    A += (size_t)bz * strA;
    B += (size_t)bz * strB;
    C += (size_t)bz * strC;
    if (resid) resid += (size_t)bz * strR;
    const int m0 = blockIdx.y * 128;
    const int n0 = blockIdx.x * 128;

    const int warp = tid >> 5, lane = tid & 31;
    const int wm = warp & 1, wn = warp >> 1;     // 2 x 4 warps
    const int g = lane >> 2, t = lane & 3;       // fragment coords
    const int lr = tid >> 1, hf = tid & 1;       // loader: row 0..127, half 0/1

    float d[4][4][4];
    #pragma unroll
    for (int i = 0; i < 4; i++)
        #pragma unroll
        for (int j = 0; j < 4; j++)
            #pragma unroll
            for (int r = 0; r < 4; r++) d[i][j][r] = 0.f;

    const int nk = K / 16;
    float4 paL, paH, pbL, pbH;

    // load + pack + store tile 0 (each thread: half-row of A and B, 8 floats)
    paL = *(const float4*)&A[(size_t)(m0 + lr) * lda + hf * 8];
    paH = *(const float4*)&A[(size_t)(m0 + lr) * lda + hf * 8 + 4];
    pbL = *(const float4*)&B[(size_t)(n0 + lr) * ldb + hf * 8];
    pbH = *(const float4*)&B[(size_t)(n0 + lr) * ldb + hf * 8 + 4];
    {
        uint4 wv;
        wv.x = pk_bf16(paL.x, paL.y); wv.y = pk_bf16(paL.z, paL.w);
        wv.z = pk_bf16(paH.x, paH.y); wv.w = pk_bf16(paH.z, paH.w);
        *(uint4*)&As[0][lr * GM_PAD + hf * 4] = wv;
        wv.x = pk_bf16(pbL.x, pbL.y); wv.y = pk_bf16(pbL.z, pbL.w);
        wv.z = pk_bf16(pbH.x, pbH.y); wv.w = pk_bf16(pbH.z, pbH.w);
        *(uint4*)&Bs[0][lr * GM_PAD + hf * 4] = wv;
    }
    __syncthreads();

    for (int kt = 0; kt < nk; kt++) {
        const int buf = kt & 1;
        if (kt + 1 < nk) {
            const int k0 = (kt + 1) * 16 + hf * 8;
            paL = *(const float4*)&A[(size_t)(m0 + lr) * lda + k0];
            paH = *(const float4*)&A[(size_t)(m0 + lr) * lda + k0 + 4];
            pbL = *(const float4*)&B[(size_t)(n0 + lr) * ldb + k0];
            pbH = *(const float4*)&B[(size_t)(n0 + lr) * ldb + k0 + 4];
        }
        {
            uint32_t af[4][4], bf[4][2];
            #pragma unroll
            for (int mt = 0; mt < 4; mt++) {
                const uint32_t* ap = &As[buf][(wm * 64 + mt * 16 + g) * GM_PAD + t];
                af[mt][0] = ap[0];
                af[mt][1] = ap[8 * GM_PAD];
                af[mt][2] = ap[4];
                af[mt][3] = ap[8 * GM_PAD + 4];
            }
            #pragma unroll
            for (int nt = 0; nt < 4; nt++) {
                const uint32_t* bp = &Bs[buf][(wn * 32 + nt * 8 + g) * GM_PAD + t];
                bf[nt][0] = bp[0];
                bf[nt][1] = bp[4];
            }
            #pragma unroll
            for (int mt = 0; mt < 4; mt++)
                #pragma unroll
                for (int nt = 0; nt < 4; nt++)
                    mma16n8k16(d[mt][nt], af[mt], bf[nt][0], bf[nt][1]);
        }
        if (kt + 1 < nk) {
            __syncthreads();
            const int nb = buf ^ 1;
            uint4 wv;
            wv.x = pk_bf16(paL.x, paL.y); wv.y = pk_bf16(paL.z, paL.w);
            wv.z = pk_bf16(paH.x, paH.y); wv.w = pk_bf16(paH.z, paH.w);
            *(uint4*)&As[nb][lr * GM_PAD + hf * 4] = wv;
            wv.x = pk_bf16(pbL.x, pbL.y); wv.y = pk_bf16(pbL.z, pbL.w);
            wv.z = pk_bf16(pbH.x, pbH.y); wv.w = pk_bf16(pbH.z, pbH.w);
            *(uint4*)&Bs[nb][lr * GM_PAD + hf * 4] = wv;
            __syncthreads();
        }
    }

    // epilogue: D fragment rows g/g+8, cols 2t/2t+1 per 16x8 tile
    #pragma unroll
    for (int mt = 0; mt < 4; mt++) {
        #pragma unroll
        for (int h = 0; h < 2; h++) {
            const int m = m0 + wm * 64 + mt * 16 + g + h * 8;
            const float bm = bias_m ? bias_m[m] : 0.f;
            #pragma unroll
            for (int nt = 0; nt < 4; nt++) {
                const int n = n0 + wn * 32 + nt * 8 + t * 2;
                const size_t off = (size_t)m * ldc + n;
                float v0 = d[mt][nt][h * 2 + 0] * alpha + bm;
                float v1 = d[mt][nt][h * 2 + 1] * alpha + bm;
                if (bias_n) { v0 += bias_n[n]; v1 += bias_n[n + 1]; }
                if (resid)  { v0 += resid[off]; v1 += resid[off + 1]; }
                *(float2*)&C[off] = make_float2(v0, v1);
            }
        }
    }
}

// ---------------- v transpose: qkv[:, :, 512:768] -> vT [B,C,N] -------------
__global__ void transpose_v_kernel(const float* __restrict__ qkv,
                                   float* __restrict__ vT)
{
    __shared__ float t[32][33];
    const int b = blockIdx.z;
    const int n0 = blockIdx.y * 32;
    const int c0 = blockIdx.x * 32;
    const float* src = qkv + (size_t)b * NSP * 3 * CCH;
    float* dst = vT + (size_t)b * CCH * NSP;
    const int x = threadIdx.x, y = threadIdx.y;   // 32x8
    #pragma unroll
    for (int j = 0; j < 32; j += 8)
        t[y + j][x] = src[(size_t)(n0 + y + j) * (3 * CCH) + 2 * CCH + c0 + x];
    __syncthreads();
    #pragma unroll
    for (int j = 0; j < 32; j += 8)
        dst[(size_t)(c0 + y + j) * NSP + n0 + x] = t[x][y + j];
}

// ---------------- row softmax ----------------
__global__ void softmax_kernel(float* __restrict__ S)
{
    __shared__ float row[NSP];
    __shared__ float red[8];
    const size_t base = (size_t)blockIdx.x * NSP;
    const int tid = threadIdx.x;

    float4* r4 = (float4*)row;
    float4* s4 = (float4*)(S + base);

    float mx = -1e30f;
    for (int i = tid; i < NSP / 4; i += 256) {
        float4 v = s4[i];
        r4[i] = v;
        mx = fmaxf(mx, fmaxf(fmaxf(v.x, v.y), fmaxf(v.z, v.w)));
    }
    #pragma unroll
    for (int o = 16; o > 0; o >>= 1) mx = fmaxf(mx, __shfl_xor_sync(0xffffffffu, mx, o));
    if ((tid & 31) == 0) red[tid >> 5] = mx;
    __syncthreads();
    if (tid == 0) {
        float m = red[0];
        #pragma unroll
        for (int i = 1; i < 8; i++) m = fmaxf(m, red[i]);
        red[0] = m;
    }
    __syncthreads();
    const float bmax = red[0];
    __syncthreads();

    float sum = 0.f;
    for (int i = tid; i < NSP / 4; i += 256) {
        float4 v = r4[i];
        v.x = __expf(v.x - bmax); v.y = __expf(v.y - bmax);
        v.z = __expf(v.z - bmax); v.w = __expf(v.w - bmax);
        r4[i] = v;
        sum += v.x + v.y + v.z + v.w;
    }
    #pragma unroll
    for (int o = 16; o > 0; o >>= 1) sum += __shfl_xor_sync(0xffffffffu, sum, o);
    if ((tid & 31) == 0) red[tid >> 5] = sum;
    __syncthreads();
    if (tid == 0) {
        float tt = 0.f;
        #pragma unroll
        for (int i = 0; i < 8; i++) tt += red[i];
        red[0] = tt;
    }
    __syncthreads();
    const float inv = 1.f / red[0];
    for (int i = tid; i < NSP / 4; i += 256) {
        float4 v = r4[i];
        v.x *= inv; v.y *= inv; v.z *= inv; v.w *= inv;
        s4[i] = v;
    }
}

// ---------------- launch ----------------
extern "C" void kernel_launch(void* const* d_in, const int* in_sizes, int n_in,
                              void* d_out, int out_size)
{
    const float* x      = (const float*)d_in[0];
    const float* norm_w = (const float*)d_in[1];
    const float* norm_b = (const float*)d_in[2];
    const float* qkv_w  = (const float*)d_in[3];
    const float* qkv_b  = (const float*)d_in[4];
    const float* proj_w = (const float*)d_in[5];
    const float* proj_b = (const float*)d_in[6];
    float* out = (float*)d_out;

    float *h, *qkv, *S, *vT, *hout;
    cudaGetSymbolAddress((void**)&h,    g_h);
    cudaGetSymbolAddress((void**)&qkv,  g_qkv);
    cudaGetSymbolAddress((void**)&S,    g_S);
    cudaGetSymbolAddress((void**)&vT,   g_vT);
    cudaGetSymbolAddress((void**)&hout, g_hout);

    const long long CN  = (long long)CCH * NSP;       // 2,097,152
    const long long C3N = 3LL * CN;
    const long long NN  = (long long)NSP * NSP;
    const float scale = 0.0625f;                      // C^-0.5

    // 1) GroupNorm -> h [B,N,C]
    groupnorm_t_kernel<<<BATCH * GROUPS, 256>>>(x, norm_w, norm_b, h);

    // 2) qkv[token,o] = sum_c h[token,c] qkv_w[o,c] + qkv_b[o]
    {
        dim3 grid((3 * CCH) / 128, NSP / 128, BATCH);
        tgemm_kernel<<<grid, 256>>>(
            h, qkv_w, qkv, CCH, CCH, CCH, 3 * CCH,
            CN, 0LL, C3N, 1.f, nullptr, qkv_b, nullptr, 0LL);
    }

    // 3) S[nq,nk] = scale * sum_c q[nq,c] k[nk,c]
    {
        dim3 grid(NSP / 128, NSP / 128, BATCH);
        tgemm_kernel<<<grid, 256>>>(
            qkv, qkv + CCH, S, CCH, 3 * CCH, 3 * CCH, NSP,
            C3N, C3N, NN, scale, nullptr, nullptr, nullptr, 0LL);
    }

    // 4) softmax rows
    softmax_kernel<<<BATCH * NSP, 256>>>(S);

    // 5) vT [B,C,N]
    {
        dim3 grid(CCH / 32, NSP / 32, BATCH);
        transpose_v_kernel<<<grid, dim3(32, 8)>>>(qkv, vT);
    }

    // 6) hout[n,c] = sum_m S[n,m] vT[c,m]
    {
        dim3 grid(CCH / 128, NSP / 128, BATCH);
        tgemm_kernel<<<grid, 256>>>(
            S, vT, hout, NSP, NSP, NSP, CCH,
            NN, CN, CN, 1.f, nullptr, nullptr, nullptr, 0LL);
    }

    // 7) out[c_out,n] = sum_c proj_w[c_out,c] hout[n,c] + proj_b[c_out] + x
    {
        dim3 grid(NSP / 128, CCH / 128, BATCH);
        tgemm_kernel<<<grid, 256>>>(
            proj_w, hout, out, CCH, CCH, CCH, NSP,
            0LL, CN, CN, 1.f, proj_b, nullptr, x, CN);
    }
}

// round 17
// speedup vs baseline: 5.0659x; 1.7756x over previous
#include <cuda_runtime.h>
#include <cuda_bf16.h>
#include <cstdint>
#include <cstddef>

#define BATCH 2
#define CCH   256
#define NSP   8192
#define GROUPS 32
#define CPG    8
#define GN_EPS 1e-5f

// ---------------- scratch (static device globals; no allocs) ----------------
__device__ float         g_h   [BATCH * NSP * CCH];       // 16 MB fp32 [B,N,C]
__device__ __nv_bfloat16 g_qkv [BATCH * NSP * 3 * CCH];   // 24 MB bf16 [B,N,768]
__device__ float         g_S   [134217728];               // 512 MB fp32 [B,N,N] logits
__device__ __nv_bfloat16 g_Sb  [134217728];               // 256 MB bf16 softmaxed
__device__ __nv_bfloat16 g_vT  [BATCH * CCH * NSP];       // 8 MB  bf16 [B,C,N]
__device__ float         g_hout[BATCH * NSP * CCH];       // 16 MB fp32 [B,N,C]

// ---------------- helpers (sm_80-baseline PTX only) -------------------------
__device__ __forceinline__ uint32_t pk_bf16(float a, float b) {
    __nv_bfloat162 h = __floats2bfloat162_rn(a, b);
    return *(uint32_t*)&h;
}
__device__ __forceinline__ void mma16n8k16(float* d, const uint32_t* a,
                                           uint32_t b0, uint32_t b1) {
    asm volatile(
        "mma.sync.aligned.m16n8k16.row.col.f32.bf16.bf16.f32 "
        "{%0,%1,%2,%3}, {%4,%5,%6,%7}, {%8,%9}, {%0,%1,%2,%3};"
        : "+f"(d[0]), "+f"(d[1]), "+f"(d[2]), "+f"(d[3])
        : "r"(a[0]), "r"(a[1]), "r"(a[2]), "r"(a[3]), "r"(b0), "r"(b1));
}
#define LDSM4(r0, r1, r2, r3, addr) \
    asm volatile("ldmatrix.sync.aligned.m8n8.x4.shared.b16 {%0,%1,%2,%3}, [%4];" \
        : "=r"(r0), "=r"(r1), "=r"(r2), "=r"(r3) : "r"(addr))
#define CP_ASYNC16(dst, src) \
    asm volatile("cp.async.cg.shared.global [%0], [%1], 16;" :: "r"(dst), "l"(src))
#define CP_COMMIT() asm volatile("cp.async.commit_group;" ::: "memory")
#define CP_WAIT(n)  asm volatile("cp.async.wait_group %0;" :: "n"(n) : "memory")

// ---------------- GroupNorm -> token-major h [B,N,C] fp32 -------------------
__global__ void groupnorm_t_kernel(const float* __restrict__ x,
                                   const float* __restrict__ w,
                                   const float* __restrict__ b,
                                   float* __restrict__ h)
{
    const int blk = blockIdx.x;
    const int bi  = blk / GROUPS;
    const int g   = blk % GROUPS;
    const size_t xbase = (size_t)blk * (CPG * NSP);
    const int tid = threadIdx.x;

    const float4* x4 = (const float4*)(x + xbase);
    float s = 0.f, ss = 0.f;
    for (int i = tid; i < (CPG * NSP) / 4; i += 256) {
        float4 v = x4[i];
        s  += v.x + v.y + v.z + v.w;
        ss += v.x*v.x + v.y*v.y + v.z*v.z + v.w*v.w;
    }
    __shared__ float rs[8], rss[8];
    #pragma unroll
    for (int o = 16; o > 0; o >>= 1) {
        s  += __shfl_down_sync(0xffffffffu, s,  o);
        ss += __shfl_down_sync(0xffffffffu, ss, o);
    }
    if ((tid & 31) == 0) { rs[tid >> 5] = s; rss[tid >> 5] = ss; }
    __syncthreads();
    if (tid == 0) {
        float a = 0.f, c = 0.f;
        #pragma unroll
        for (int i = 0; i < 8; i++) { a += rs[i]; c += rss[i]; }
        rs[0] = a; rss[0] = c;
    }
    __syncthreads();
    const float mean = rs[0] / (float)(CPG * NSP);
    const float var  = rss[0] / (float)(CPG * NSP) - mean * mean;
    const float rstd = rsqrtf(var + GN_EPS);

    __shared__ float smt[8][136];
    const int c  = tid >> 5;
    const int q  = tid & 31;
    const float sc = w[g * CPG + c] * rstd;
    const float of = b[g * CPG + c] - mean * sc;
    float* hb = h + (size_t)bi * NSP * CCH;
    const int half = tid & 1;
    const int nn   = tid >> 1;

    for (int t = 0; t < NSP / 128; t++) {
        float4 v = *(const float4*)&x[xbase + (size_t)c * NSP + t * 128 + q * 4];
        v.x = v.x * sc + of; v.y = v.y * sc + of;
        v.z = v.z * sc + of; v.w = v.w * sc + of;
        *(float4*)&smt[c][q * 4] = v;
        __syncthreads();
        float4 o;
        o.x = smt[half * 4 + 0][nn];
        o.y = smt[half * 4 + 1][nn];
        o.z = smt[half * 4 + 2][nn];
        o.w = smt[half * 4 + 3][nn];
        *(float4*)&hb[(size_t)(t * 128 + nn) * CCH + g * CPG + half * 4] = o;
        __syncthreads();
    }
}

// ---------------- fp32-operand GEMM (GEMM2 / GEMM7), optional bf16 out ------
#define GM_PAD 12
__global__ __launch_bounds__(256, 2)
void tgemm_kernel(const float* __restrict__ A, const float* __restrict__ B,
                  void* __restrict__ Cv,
                  int K, int lda, int ldb, int ldc,
                  long long strA, long long strB, long long strC,
                  float alpha,
                  const float* __restrict__ bias_n,
                  const float* __restrict__ resid, long long strR,
                  int bf16_out)
{
    __shared__ uint32_t As[2][128 * GM_PAD];
    __shared__ uint32_t Bs[2][128 * GM_PAD];

    const int tid = threadIdx.x;
    const int bz = blockIdx.z;
    A += (size_t)bz * strA;
    B += (size_t)bz * strB;
    if (resid) resid += (size_t)bz * strR;
    const int m0 = blockIdx.y * 128;
    const int n0 = blockIdx.x * 128;

    const int warp = tid >> 5, lane = tid & 31;
    const int wm = warp & 1, wn = warp >> 1;
    const int g = lane >> 2, t = lane & 3;
    const int lr = tid >> 1, hf = tid & 1;

    float d[4][4][4] = {};
    const int nk = K / 16;
    float4 paL, paH, pbL, pbH;

    paL = *(const float4*)&A[(size_t)(m0 + lr) * lda + hf * 8];
    paH = *(const float4*)&A[(size_t)(m0 + lr) * lda + hf * 8 + 4];
    pbL = *(const float4*)&B[(size_t)(n0 + lr) * ldb + hf * 8];
    pbH = *(const float4*)&B[(size_t)(n0 + lr) * ldb + hf * 8 + 4];
    {
        uint4 wv;
        wv.x = pk_bf16(paL.x, paL.y); wv.y = pk_bf16(paL.z, paL.w);
        wv.z = pk_bf16(paH.x, paH.y); wv.w = pk_bf16(paH.z, paH.w);
        *(uint4*)&As[0][lr * GM_PAD + hf * 4] = wv;
        wv.x = pk_bf16(pbL.x, pbL.y); wv.y = pk_bf16(pbL.z, pbL.w);
        wv.z = pk_bf16(pbH.x, pbH.y); wv.w = pk_bf16(pbH.z, pbH.w);
        *(uint4*)&Bs[0][lr * GM_PAD + hf * 4] = wv;
    }
    __syncthreads();

    for (int kt = 0; kt < nk; kt++) {
        const int buf = kt & 1;
        if (kt + 1 < nk) {
            const int k0 = (kt + 1) * 16 + hf * 8;
            paL = *(const float4*)&A[(size_t)(m0 + lr) * lda + k0];
            paH = *(const float4*)&A[(size_t)(m0 + lr) * lda + k0 + 4];
            pbL = *(const float4*)&B[(size_t)(n0 + lr) * ldb + k0];
            pbH = *(const float4*)&B[(size_t)(n0 + lr) * ldb + k0 + 4];
        }
        {
            uint32_t af[4][4], bf[4][2];
            #pragma unroll
            for (int mt = 0; mt < 4; mt++) {
                const uint32_t* ap = &As[buf][(wm * 64 + mt * 16 + g) * GM_PAD + t];
                af[mt][0] = ap[0];
                af[mt][1] = ap[8 * GM_PAD];
                af[mt][2] = ap[4];
                af[mt][3] = ap[8 * GM_PAD + 4];
            }
            #pragma unroll
            for (int nt = 0; nt < 4; nt++) {
                const uint32_t* bp = &Bs[buf][(wn * 32 + nt * 8 + g) * GM_PAD + t];
                bf[nt][0] = bp[0];
                bf[nt][1] = bp[4];
            }
            #pragma unroll
            for (int mt = 0; mt < 4; mt++)
                #pragma unroll
                for (int nt = 0; nt < 4; nt++)
                    mma16n8k16(d[mt][nt], af[mt], bf[nt][0], bf[nt][1]);
        }
        if (kt + 1 < nk) {
            __syncthreads();
            const int nb = buf ^ 1;
            uint4 wv;
            wv.x = pk_bf16(paL.x, paL.y); wv.y = pk_bf16(paL.z, paL.w);
            wv.z = pk_bf16(paH.x, paH.y); wv.w = pk_bf16(paH.z, paH.w);
            *(uint4*)&As[nb][lr * GM_PAD + hf * 4] = wv;
            wv.x = pk_bf16(pbL.x, pbL.y); wv.y = pk_bf16(pbL.z, pbL.w);
            wv.z = pk_bf16(pbH.x, pbH.y); wv.w = pk_bf16(pbH.z, pbH.w);
            *(uint4*)&Bs[nb][lr * GM_PAD + hf * 4] = wv;
            __syncthreads();
        }
    }

    float* Cf = (float*)Cv;
    __nv_bfloat16* Cb = (__nv_bfloat16*)Cv;
    if (bf16_out) Cb += (size_t)bz * strC; else Cf += (size_t)bz * strC;

    #pragma unroll
    for (int mt = 0; mt < 4; mt++) {
        #pragma unroll
        for (int h = 0; h < 2; h++) {
            const int m = m0 + wm * 64 + mt * 16 + g + h * 8;
            #pragma unroll
            for (int nt = 0; nt < 4; nt++) {
                const int n = n0 + wn * 32 + nt * 8 + t * 2;
                const size_t off = (size_t)m * ldc + n;
                float v0 = d[mt][nt][h * 2 + 0] * alpha;
                float v1 = d[mt][nt][h * 2 + 1] * alpha;
                if (bias_n) { v0 += bias_n[n]; v1 += bias_n[n + 1]; }
                if (resid)  { v0 += resid[off]; v1 += resid[off + 1]; }
                if (bf16_out) *(uint32_t*)&Cb[off] = pk_bf16(v0, v1);
                else          *(float2*)&Cf[off] = make_float2(v0, v1);
            }
        }
    }
}

// ---------------- bf16-operand GEMM (GEMM3 / GEMM6): cp.async + ldmatrix ----
// BM=BN=128, BK=32, 3-stage cp.async ring. A [M,K] lda; B [N,K] ldb; C fp32.
// Smem rows: 16 data words (32 bf16) + 4 pad = 20 words (80 B); the 8 rows of
// each ldmatrix 8x8 tile land on banks 20r mod 32 = all distinct quads.
#define BG_STAGE_W (128 * 20)            // words per stage per operand
#define BG_SMEM (3 * 2 * BG_STAGE_W * 4) // 61440 bytes

__global__ __launch_bounds__(256, 2)
void bgemm_kernel(const __nv_bfloat16* __restrict__ A,
                  const __nv_bfloat16* __restrict__ B,
                  float* __restrict__ C,
                  int K, int lda, int ldb, int ldc,
                  long long strA, long long strB, long long strC,
                  float alpha)
{
    extern __shared__ uint32_t sm[];
    const uint32_t smb = (uint32_t)__cvta_generic_to_shared(sm);
    const int tid = threadIdx.x;
    const int bz = blockIdx.z;
    A += (size_t)bz * strA;
    B += (size_t)bz * strB;
    C += (size_t)bz * strC;
    const int m0 = blockIdx.y * 128;
    const int n0 = blockIdx.x * 128;

    const int warp = tid >> 5, lane = tid & 31;
    const int wm = warp & 1, wn = warp >> 1;     // 2 x 4 warps, warp tile 64x32
    const int g = lane >> 2, t = lane & 3;       // epilogue frag coords
    const int q8 = lane >> 3, r8 = lane & 7;     // ldmatrix lane coords

    // loader: 512 16B-chunks per operand per stage; thread does chunks tid, tid+256
    const int lrow0 = tid >> 2,        lch = tid & 3;
    const int lrow1 = (tid + 256) >> 2;
    const uint32_t Abase = smb;
    const uint32_t Bbase = smb + 3 * BG_STAGE_W * 4;
    const __nv_bfloat16* Ag = A + (size_t)m0 * lda;
    const __nv_bfloat16* Bg = B + (size_t)n0 * ldb;

    float d[4][4][4] = {};
    const int nk = K / 32;

    // ldmatrix per-lane row/koff components
    const uint32_t a_row = (uint32_t)(wm * 64 + (q8 & 1) * 8 + r8);
    const uint32_t a_ko  = (uint32_t)((q8 >> 1) * 16);
    const uint32_t b_row = (uint32_t)(wn * 32 + (q8 >> 1) * 8 + r8);
    const uint32_t b_ko  = (uint32_t)((q8 & 1) * 16);

    #define BG_ISSUE(ktv) do {                                                   \
        const int _st = (ktv) % 3;                                               \
        const uint32_t _Ast = Abase + _st * (BG_STAGE_W * 4);                    \
        const uint32_t _Bst = Bbase + _st * (BG_STAGE_W * 4);                    \
        const int _k0 = (ktv) * 32;                                              \
        CP_ASYNC16(_Ast + lrow0 * 80 + lch * 16, Ag + (size_t)lrow0 * lda + _k0 + lch * 8); \
        CP_ASYNC16(_Ast + lrow1 * 80 + lch * 16, Ag + (size_t)lrow1 * lda + _k0 + lch * 8); \
        CP_ASYNC16(_Bst + lrow0 * 80 + lch * 16, Bg + (size_t)lrow0 * ldb + _k0 + lch * 8); \
        CP_ASYNC16(_Bst + lrow1 * 80 + lch * 16, Bg + (size_t)lrow1 * ldb + _k0 + lch * 8); \
        CP_COMMIT();                                                             \
    } while (0)

    BG_ISSUE(0);
    if (nk > 1) BG_ISSUE(1);

    for (int kt = 0; kt < nk; kt++) {
        if (kt + 1 < nk) CP_WAIT(1); else CP_WAIT(0);
        __syncthreads();
        if (kt + 2 < nk) BG_ISSUE(kt + 2);
        const int st = kt % 3;
        const uint32_t Ast = Abase + st * (BG_STAGE_W * 4);
        const uint32_t Bst = Bbase + st * (BG_STAGE_W * 4);
        #pragma unroll
        for (int ks = 0; ks < 2; ks++) {
            uint32_t af[4][4], bf[4][2];
            #pragma unroll
            for (int mt = 0; mt < 4; mt++) {
                uint32_t ad = Ast + (a_row + mt * 16) * 80 + ks * 32 + a_ko;
                LDSM4(af[mt][0], af[mt][1], af[mt][2], af[mt][3], ad);
            }
            #pragma unroll
            for (int p = 0; p < 2; p++) {
                uint32_t bd = Bst + (b_row + p * 16) * 80 + ks * 32 + b_ko;
                LDSM4(bf[2*p][0], bf[2*p][1], bf[2*p+1][0], bf[2*p+1][1], bd);
            }
            #pragma unroll
            for (int mt = 0; mt < 4; mt++)
                #pragma unroll
                for (int nt = 0; nt < 4; nt++)
                    mma16n8k16(d[mt][nt], af[mt], bf[nt][0], bf[nt][1]);
        }
    }
    #undef BG_ISSUE

    #pragma unroll
    for (int mt = 0; mt < 4; mt++) {
        #pragma unroll
        for (int h = 0; h < 2; h++) {
            const int m = m0 + wm * 64 + mt * 16 + g + h * 8;
            #pragma unroll
            for (int nt = 0; nt < 4; nt++) {
                const int n = n0 + wn * 32 + nt * 8 + t * 2;
                const size_t off = (size_t)m * ldc + n;
                *(float2*)&C[off] = make_float2(d[mt][nt][h*2] * alpha,
                                                d[mt][nt][h*2+1] * alpha);
            }
        }
    }
}

// ---------------- v transpose (bf16): qkv[:, :, 512:768] -> vT [B,C,N] ------
__global__ void transpose_v_kernel(const __nv_bfloat16* __restrict__ qkv,
                                   __nv_bfloat16* __restrict__ vT)
{
    __shared__ __nv_bfloat16 tsm[32][34];
    const int b = blockIdx.z;
    const int n0 = blockIdx.y * 32;
    const int c0 = blockIdx.x * 32;
    const __nv_bfloat16* src = qkv + (size_t)b * NSP * 3 * CCH;
    __nv_bfloat16* dst = vT + (size_t)b * CCH * NSP;
    const int x = threadIdx.x, y = threadIdx.y;
    #pragma unroll
    for (int j = 0; j < 32; j += 8)
        tsm[y + j][x] = src[(size_t)(n0 + y + j) * (3 * CCH) + 2 * CCH + c0 + x];
    __syncthreads();
    #pragma unroll
    for (int j = 0; j < 32; j += 8)
        dst[(size_t)(c0 + y + j) * NSP + n0 + x] = tsm[x][y + j];
}

// ---------------- row softmax: fp32 logits in, bf16 weights out -------------
__global__ void softmax_kernel(const float* __restrict__ S,
                               __nv_bfloat16* __restrict__ Sb)
{
    __shared__ float row[NSP];
    __shared__ float red[8];
    const size_t base = (size_t)blockIdx.x * NSP;
    const int tid = threadIdx.x;

    float4* r4 = (float4*)row;
    const float4* s4 = (const float4*)(S + base);

    float mx = -1e30f;
    for (int i = tid; i < NSP / 4; i += 256) {
        float4 v = s4[i];
        r4[i] = v;
        mx = fmaxf(mx, fmaxf(fmaxf(v.x, v.y), fmaxf(v.z, v.w)));
    }
    #pragma unroll
    for (int o = 16; o > 0; o >>= 1) mx = fmaxf(mx, __shfl_xor_sync(0xffffffffu, mx, o));
    if ((tid & 31) == 0) red[tid >> 5] = mx;
    __syncthreads();
    if (tid == 0) {
        float m = red[0];
        #pragma unroll
        for (int i = 1; i < 8; i++) m = fmaxf(m, red[i]);
        red[0] = m;
    }
    __syncthreads();
    const float bmax = red[0];
    __syncthreads();

    float sum = 0.f;
    for (int i = tid; i < NSP / 4; i += 256) {
        float4 v = r4[i];
        v.x = __expf(v.x - bmax); v.y = __expf(v.y - bmax);
        v.z = __expf(v.z - bmax); v.w = __expf(v.w - bmax);
        r4[i] = v;
        sum += v.x + v.y + v.z + v.w;
    }
    #pragma unroll
    for (int o = 16; o > 0; o >>= 1) sum += __shfl_xor_sync(0xffffffffu, sum, o);
    if ((tid & 31) == 0) red[tid >> 5] = sum;
    __syncthreads();
    if (tid == 0) {
        float tt = 0.f;
        #pragma unroll
        for (int i = 0; i < 8; i++) tt += red[i];
        red[0] = tt;
    }
    __syncthreads();
    const float inv = 1.f / red[0];
    uint2* o2 = (uint2*)(Sb + base);
    for (int i = tid; i < NSP / 4; i += 256) {
        float4 v = r4[i];
        uint2 w;
        w.x = pk_bf16(v.x * inv, v.y * inv);
        w.y = pk_bf16(v.z * inv, v.w * inv);
        o2[i] = w;
    }
}

// ---------------- launch ----------------
extern "C" void kernel_launch(void* const* d_in, const int* in_sizes, int n_in,
                              void* d_out, int out_size)
{
    const float* x      = (const float*)d_in[0];
    const float* norm_w = (const float*)d_in[1];
    const float* norm_b = (const float*)d_in[2];
    const float* qkv_w  = (const float*)d_in[3];
    const float* qkv_b  = (const float*)d_in[4];
    const float* proj_w = (const float*)d_in[5];
    const float* proj_b = (const float*)d_in[6];
    float* out = (float*)d_out;

    float *h, *S, *hout;
    __nv_bfloat16 *qkv, *Sb, *vT;
    cudaGetSymbolAddress((void**)&h,    g_h);
    cudaGetSymbolAddress((void**)&qkv,  g_qkv);
    cudaGetSymbolAddress((void**)&S,    g_S);
    cudaGetSymbolAddress((void**)&Sb,   g_Sb);
    cudaGetSymbolAddress((void**)&vT,   g_vT);
    cudaGetSymbolAddress((void**)&hout, g_hout);

    cudaFuncSetAttribute(bgemm_kernel,
                         cudaFuncAttributeMaxDynamicSharedMemorySize, BG_SMEM);

    const long long CN   = (long long)CCH * NSP;
    const long long C3N  = 3LL * CN;
    const long long NN   = (long long)NSP * NSP;
    const float scale = 0.0625f;

    // 1) GroupNorm -> h fp32 [B,N,C]
    groupnorm_t_kernel<<<BATCH * GROUPS, 256>>>(x, norm_w, norm_b, h);

    // 2) qkv (bf16) = h @ qkv_w^T + qkv_b
    {
        dim3 grid((3 * CCH) / 128, NSP / 128, BATCH);
        tgemm_kernel<<<grid, 256>>>(
            h, qkv_w, qkv, CCH, CCH, CCH, 3 * CCH,
            CN, 0LL, C3N, 1.f, qkv_b, nullptr, 0LL, 1);
    }

    // 3) S (fp32) = scale * q k^T   (bf16 operands, cp.async+ldmatrix)
    {
        dim3 grid(NSP / 128, NSP / 128, BATCH);
        bgemm_kernel<<<grid, 256, BG_SMEM>>>(
            qkv, qkv + CCH, S, CCH, 3 * CCH, 3 * CCH, NSP,
            C3N, C3N, NN, scale);
    }

    // 4) softmax: fp32 in -> bf16 out
    softmax_kernel<<<BATCH * NSP, 256>>>(S, Sb);

    // 5) vT bf16 [B,C,N]
    {
        dim3 grid(CCH / 32, NSP / 32, BATCH);
        transpose_v_kernel<<<grid, dim3(32, 8)>>>(qkv, vT);
    }

    // 6) hout (fp32) = Sb @ vT^T   (bf16 operands)
    {
        dim3 grid(CCH / 128, NSP / 128, BATCH);
        bgemm_kernel<<<grid, 256, BG_SMEM>>>(
            Sb, vT, hout, NSP, NSP, NSP, CCH,
            NN, CN, CN, 1.f);
    }

    // 7) out = x + proj_w @ hout + proj_b  (fp32 path)
    {
        dim3 grid(NSP / 128, CCH / 128, BATCH);
        tgemm_kernel<<<grid, 256>>>(
            proj_w, hout, out, CCH, CCH, CCH, NSP,
            0LL, CN, CN, 1.f, proj_b, x, CN, 0);
    }
}